// round 6
// baseline (speedup 1.0000x reference)
#include <cuda_runtime.h>
#include <math.h>

#define BATCH 2
#define HH 256
#define WW 256
#define CIN 64
#define HEADS 8
#define HD 512

// ---------------- scratch (device globals; no runtime allocation) ----------------
__device__ float g_S[BATCH * 64 * 64];        // xd^T xd per batch
__device__ float g_SQ[BATCH * 64 * HD];       // S @ Wq
__device__ float g_nk[BATCH * HD];
__device__ float g_nq[BATCH * HD];
__device__ float g_M[BATCH * 64 * 64];        // Wv @ A^T @ Wproj per batch
__device__ float g_Wp[64 * 64];               // Wv @ Wc1d
__device__ float g_P[(size_t)BATCH * HH * WW * 64];  // p_pre (33.5 MB)

// ---------------- K0: zero accumulated buffers ----------------
__global__ void k0_zero() {
    int i = blockIdx.x * blockDim.x + threadIdx.x;
    if (i < BATCH * 4096) { g_S[i] = 0.f; g_M[i] = 0.f; }
    if (i < 4096) g_Wp[i] = 0.f;
}

// ---------------- K1: S_b = xd^T xd, xd = avgpool2x2(x) ----------------
// grid 64: 32 blocks/batch, each owns 4 ds-rows (512 tokens)
__global__ void k1_S(const float* __restrict__ x) {
    __shared__ float xs[16 * 64];
    int b  = blockIdx.x >> 5;
    int r0 = (blockIdx.x & 31) * 4;
    int tid = threadIdx.x;
    int ti = tid >> 4, tj = tid & 15;
    float acc[4][4];
#pragma unroll
    for (int r = 0; r < 4; r++)
#pragma unroll
        for (int s = 0; s < 4; s++) acc[r][s] = 0.f;

    int c   = tid & 63;
    int tl0 = tid >> 6;  // 0..3
    for (int g = 0; g < 32; g++) {
        int row  = r0 + (g >> 3);
        int col0 = (g & 7) * 16;
#pragma unroll
        for (int it = 0; it < 4; it++) {
            int tl = it * 4 + tl0;
            int gx = (col0 + tl) * 2;
            int gy = row * 2;
            const float* p0 = x + (((size_t)b * HH + gy) * WW + gx) * 64 + c;
            xs[tl * 64 + c] = 0.25f * (p0[0] + p0[64] + p0[WW * 64] + p0[WW * 64 + 64]);
        }
        __syncthreads();
#pragma unroll
        for (int t = 0; t < 16; t++) {
            float4 av = *(const float4*)&xs[t * 64 + 4 * ti];
            float4 bv = *(const float4*)&xs[t * 64 + 4 * tj];
            float a4[4] = {av.x, av.y, av.z, av.w};
            float b4[4] = {bv.x, bv.y, bv.z, bv.w};
#pragma unroll
            for (int r = 0; r < 4; r++)
#pragma unroll
                for (int s = 0; s < 4; s++) acc[r][s] += a4[r] * b4[s];
        }
        __syncthreads();
    }
    float* Sb = g_S + b * 4096;
#pragma unroll
    for (int r = 0; r < 4; r++)
#pragma unroll
        for (int s = 0; s < 4; s++)
            atomicAdd(&Sb[(4 * ti + r) * 64 + 4 * tj + s], acc[r][s]);
}

// ---------------- K2: SQ = S@Wq (stored), norms nk/nq ----------------
// grid 16: (b, h)
__global__ void k2_SQ(const float* __restrict__ Wq, const float* __restrict__ Wk) {
    __shared__ float Ss[4096];
    __shared__ float Wc[4096];
    __shared__ float n2[64];
    int b = blockIdx.x >> 3, h = blockIdx.x & 7;
    int tid = threadIdx.x, ti = tid >> 4, tj = tid & 15;
    for (int u = tid; u < 4096; u += 256) Ss[u] = g_S[b * 4096 + u];

    for (int pass = 0; pass < 2; pass++) {
        const float* Wsrc = pass ? Wk : Wq;
        for (int u = tid; u < 4096; u += 256) {
            int cc = u >> 6, j = u & 63;
            Wc[u] = Wsrc[cc * HD + h * 64 + j];
        }
        if (tid < 64) n2[tid] = 0.f;
        __syncthreads();

        float acc[4][4];
#pragma unroll
        for (int r = 0; r < 4; r++)
#pragma unroll
            for (int s = 0; s < 4; s++) acc[r][s] = 0.f;
#pragma unroll 16
        for (int cc = 0; cc < 64; cc++) {
            float4 bv = *(const float4*)&Wc[cc * 64 + 4 * tj];
            float b4[4] = {bv.x, bv.y, bv.z, bv.w};
            float a4[4];
#pragma unroll
            for (int r = 0; r < 4; r++) a4[r] = Ss[(4 * ti + r) * 64 + cc];
#pragma unroll
            for (int r = 0; r < 4; r++)
#pragma unroll
                for (int s = 0; s < 4; s++) acc[r][s] += a4[r] * b4[s];
        }
        float psum[4] = {0.f, 0.f, 0.f, 0.f};
#pragma unroll
        for (int r = 0; r < 4; r++)
#pragma unroll
            for (int s = 0; s < 4; s++)
                psum[s] += Wc[(4 * ti + r) * 64 + 4 * tj + s] * acc[r][s];
        if (!pass) {
#pragma unroll
            for (int r = 0; r < 4; r++)
#pragma unroll
                for (int s = 0; s < 4; s++)
                    g_SQ[b * 32768 + (4 * ti + r) * HD + h * 64 + 4 * tj + s] = acc[r][s];
        }
#pragma unroll
        for (int s = 0; s < 4; s++) atomicAdd(&n2[4 * tj + s], psum[s]);
        __syncthreads();
        if (tid < 64) {
            float nv = fmaxf(sqrtf(fmaxf(n2[tid], 0.f)), 1e-12f);
            (pass ? g_nk : g_nq)[b * HD + h * 64 + tid] = nv;
        }
        __syncthreads();
    }
}

// ---------------- K3: attn -> M_b, and Wp = Wv@Wc1d ----------------
// grid 16: (b, h), dynamic smem = (12288 + 128) floats
__global__ void k3_attn(const float* __restrict__ Wk, const float* __restrict__ Wq,
                        const float* __restrict__ rescale, const float* __restrict__ Wproj,
                        const float* __restrict__ Wv, const float* __restrict__ Wc1d) {
    extern __shared__ float sm3[];
    float* bufA = sm3;
    float* bufB = sm3 + 4096;
    float* bufC = sm3 + 8192;
    float* nks  = sm3 + 12288;
    float* nqs  = nks + 64;
    int b = blockIdx.x >> 3, h = blockIdx.x & 7;
    int tid = threadIdx.x, ti = tid >> 4, tj = tid & 15;

    for (int u = tid; u < 4096; u += 256) {
        int cc = u >> 6, i = u & 63;
        bufA[u] = Wk[cc * HD + h * 64 + i];              // Wk_h [c][i]
        bufB[u] = g_SQ[b * 32768 + cc * HD + h * 64 + i]; // SQ_h [c][j]
    }
    if (tid < 64) { nks[tid] = g_nk[b * HD + h * 64 + tid]; nqs[tid] = g_nq[b * HD + h * 64 + tid]; }
    __syncthreads();
    float resc = rescale[h];

    float acc[4][4];
#pragma unroll
    for (int r = 0; r < 4; r++)
#pragma unroll
        for (int s = 0; s < 4; s++) acc[r][s] = 0.f;
#pragma unroll 16
    for (int cc = 0; cc < 64; cc++) {   // G[i][j] = sum_c Wk_h[c][i] * SQ_h[c][j]
        float4 av = *(const float4*)&bufA[cc * 64 + 4 * ti];
        float4 bv = *(const float4*)&bufB[cc * 64 + 4 * tj];
        float a4[4] = {av.x, av.y, av.z, av.w}, b4[4] = {bv.x, bv.y, bv.z, bv.w};
#pragma unroll
        for (int r = 0; r < 4; r++)
#pragma unroll
            for (int s = 0; s < 4; s++) acc[r][s] += a4[r] * b4[s];
    }
#pragma unroll
    for (int r = 0; r < 4; r++)
#pragma unroll
        for (int s = 0; s < 4; s++)
            bufC[(4 * ti + r) * 64 + 4 * tj + s] =
                acc[r][s] / (nks[4 * ti + r] * nqs[4 * tj + s]) * resc;
    __syncthreads();

    // overwrite bufA with Wproj_h [i][d]; softmax rows of bufC concurrently
    for (int u = tid; u < 4096; u += 256)
        bufA[u] = Wproj[(h * 64 + (u >> 6)) * 64 + (u & 63)];
    if (tid < 64) {
        float m = -1e30f;
        for (int j = 0; j < 64; j++) m = fmaxf(m, bufC[tid * 64 + j]);
        float ss = 0.f;
        for (int j = 0; j < 64; j++) { float e = expf(bufC[tid * 64 + j] - m); bufC[tid * 64 + j] = e; ss += e; }
        float inv = 1.f / ss;
        for (int j = 0; j < 64; j++) bufC[tid * 64 + j] *= inv;
    }
    __syncthreads();

    // B[j][d] = sum_i attn[i][j] * Wproj_h[i][d]   (into regs, then bufB)
#pragma unroll
    for (int r = 0; r < 4; r++)
#pragma unroll
        for (int s = 0; s < 4; s++) acc[r][s] = 0.f;
#pragma unroll 16
    for (int i = 0; i < 64; i++) {
        float4 av = *(const float4*)&bufC[i * 64 + 4 * ti];   // j = 4ti+r
        float4 bv = *(const float4*)&bufA[i * 64 + 4 * tj];   // d = 4tj+s
        float a4[4] = {av.x, av.y, av.z, av.w}, b4[4] = {bv.x, bv.y, bv.z, bv.w};
#pragma unroll
        for (int r = 0; r < 4; r++)
#pragma unroll
            for (int s = 0; s < 4; s++) acc[r][s] += a4[r] * b4[s];
    }
    __syncthreads();   // everyone done reading bufB (G stage long done), bufC reads done
#pragma unroll
    for (int r = 0; r < 4; r++)
#pragma unroll
        for (int s = 0; s < 4; s++) bufB[(4 * ti + r) * 64 + 4 * tj + s] = acc[r][s];
    for (int u = tid; u < 4096; u += 256)
        bufC[u] = Wv[(u >> 6) * HD + h * 64 + (u & 63)];      // Wv_h [c][j]
    __syncthreads();

    // C[c][d] = sum_j Wv_h[c][j] * B[j][d] -> atomic into g_M[b]
#pragma unroll
    for (int r = 0; r < 4; r++)
#pragma unroll
        for (int s = 0; s < 4; s++) acc[r][s] = 0.f;
#pragma unroll 16
    for (int j = 0; j < 64; j++) {
        float4 bv = *(const float4*)&bufB[j * 64 + 4 * tj];
        float b4[4] = {bv.x, bv.y, bv.z, bv.w};
        float a4[4];
#pragma unroll
        for (int r = 0; r < 4; r++) a4[r] = bufC[(4 * ti + r) * 64 + j];
#pragma unroll
        for (int r = 0; r < 4; r++)
#pragma unroll
            for (int s = 0; s < 4; s++) acc[r][s] += a4[r] * b4[s];
    }
#pragma unroll
    for (int r = 0; r < 4; r++)
#pragma unroll
        for (int s = 0; s < 4; s++)
            atomicAdd(&g_M[b * 4096 + (4 * ti + r) * 64 + 4 * tj + s], acc[r][s]);

    if (b == 0) {  // Wp = Wv @ Wc1d (batch independent): blocks of batch 0 only
        __syncthreads();
        for (int u = tid; u < 4096; u += 256)
            bufA[u] = Wc1d[(h * 64 + (u >> 6)) * 64 + (u & 63)];  // [j][d]
        __syncthreads();
#pragma unroll
        for (int r = 0; r < 4; r++)
#pragma unroll
            for (int s = 0; s < 4; s++) acc[r][s] = 0.f;
#pragma unroll 16
        for (int j = 0; j < 64; j++) {
            float4 bv = *(const float4*)&bufA[j * 64 + 4 * tj];
            float b4[4] = {bv.x, bv.y, bv.z, bv.w};
            float a4[4];
#pragma unroll
            for (int r = 0; r < 4; r++) a4[r] = bufC[(4 * ti + r) * 64 + j];
#pragma unroll
            for (int r = 0; r < 4; r++)
#pragma unroll
                for (int s = 0; s < 4; s++) acc[r][s] += a4[r] * b4[s];
        }
#pragma unroll
        for (int r = 0; r < 4; r++)
#pragma unroll
            for (int s = 0; s < 4; s++)
                atomicAdd(&g_Wp[(4 * ti + r) * 64 + 4 * tj + s], acc[r][s]);
    }
}

// ---------------- K4a: p_pre = x @ Wp + bc1d -> g_P ----------------
// grid 2048 blocks x 64 pixels
__global__ void k4a_P(const float* __restrict__ x, const float* __restrict__ bc1d) {
    __shared__ float Wps[4096];
    __shared__ float xs[4096];
    __shared__ float bc[64];
    int tid = threadIdx.x;
    for (int u = tid; u < 4096; u += 256) Wps[u] = g_Wp[u];
    if (tid < 64) bc[tid] = bc1d[tid];
    size_t base = (size_t)blockIdx.x * 4096;
    const float4* src = (const float4*)(x + base);
    for (int u = tid; u < 1024; u += 256) ((float4*)xs)[u] = src[u];
    __syncthreads();

    int ti = tid >> 4, tj = tid & 15;
    float acc[4][4];
#pragma unroll
    for (int r = 0; r < 4; r++)
#pragma unroll
        for (int s = 0; s < 4; s++) acc[r][s] = 0.f;
#pragma unroll 16
    for (int cc = 0; cc < 64; cc++) {
        float4 bv = *(const float4*)&Wps[cc * 64 + 4 * tj];
        float b4[4] = {bv.x, bv.y, bv.z, bv.w};
        float a4[4];
#pragma unroll
        for (int r = 0; r < 4; r++) a4[r] = xs[(4 * ti + r) * 64 + cc];
#pragma unroll
        for (int r = 0; r < 4; r++)
#pragma unroll
            for (int s = 0; s < 4; s++) acc[r][s] += a4[r] * b4[s];
    }
#pragma unroll
    for (int r = 0; r < 4; r++) {
        float4 o;
        o.x = acc[r][0] + bc[4 * tj + 0];
        o.y = acc[r][1] + bc[4 * tj + 1];
        o.z = acc[r][2] + bc[4 * tj + 2];
        o.w = acc[r][3] + bc[4 * tj + 3];
        *(float4*)(g_P + base + (size_t)(4 * ti + r) * 64 + 4 * tj) = o;
    }
}

// ---------------- K4b: conv1+GELU+conv2 + x@M + bproj -> out ----------------
// grid 2048: (b, 32x32 tiles of 8x8). dyn smem = 25024 floats
__global__ void k4b_main(const float* __restrict__ x, const float* __restrict__ bproj,
                         const float* __restrict__ Wpe1, const float* __restrict__ Wpe2,
                         float* __restrict__ out) {
    extern __shared__ float sm4[];
    float* ps  = sm4;          // 12x12x64 = 9216
    float* p1  = ps + 9216;    // 10x10x64 = 6400
    float* xs  = p1 + 6400;    // 8x8x64   = 4096
    float* Ms  = xs + 4096;    // 4096
    float* w1  = Ms + 4096;    // 576
    float* w2  = w1 + 576;     // 576
    float* bps = w2 + 576;     // 64
    int blk = blockIdx.x;
    int b = blk >> 10;
    int rem = blk & 1023;
    int y0 = (rem >> 5) * 8, x0 = (rem & 31) * 8;
    int tid = threadIdx.x;

    for (int u = tid; u < 4096; u += 256) Ms[u] = g_M[b * 4096 + u];
    for (int u = tid; u < 576; u += 256) { w1[u] = Wpe1[u]; w2[u] = Wpe2[u]; }
    if (tid < 64) bps[tid] = bproj[tid];
    for (int u = tid; u < 1024; u += 256) {  // interior x tile (8 rows x 512 floats)
        int py = u >> 7, off = u & 127;
        const float4* src = (const float4*)(x + (((size_t)(b * HH + y0 + py)) * WW + x0) * 64);
        ((float4*)xs)[py * 128 + off] = src[off];
    }
    for (int u = tid; u < 9216; u += 256) {  // halo p_pre with zero pad
        int px = u >> 6, c = u & 63;
        int py = px / 12, pxx = px - py * 12;
        int gy = y0 - 2 + py, gx = x0 - 2 + pxx;
        float v = 0.f;
        if ((unsigned)gy < HH && (unsigned)gx < WW)
            v = g_P[(((size_t)(b * HH + gy)) * WW + gx) * 64 + c];
        ps[u] = v;
    }
    __syncthreads();

    for (int u = tid; u < 6400; u += 256) {  // conv1 + exact GELU, zero outside image
        int px = u >> 6, c = u & 63;
        int py = px / 10, pxx = px - py * 10;
        int gy = y0 - 1 + py, gx = x0 - 1 + pxx;
        float v = 0.f;
        if ((unsigned)gy < HH && (unsigned)gx < WW) {
            float a = 0.f;
#pragma unroll
            for (int ky = 0; ky < 3; ky++)
#pragma unroll
                for (int kx = 0; kx < 3; kx++)
                    a += ps[((py + ky) * 12 + pxx + kx) * 64 + c] * w1[c * 9 + ky * 3 + kx];
            v = 0.5f * a * (1.f + erff(a * 0.70710678118654752f));
        }
        p1[u] = v;
    }
    __syncthreads();

    int ti = tid >> 4, tj = tid & 15;
    float wr[4][9];
#pragma unroll
    for (int s = 0; s < 4; s++)
#pragma unroll
        for (int k = 0; k < 9; k++) wr[s][k] = w2[(4 * tj + s) * 9 + k];

    float acc[4][4];
#pragma unroll
    for (int r = 0; r < 4; r++)
#pragma unroll
        for (int s = 0; s < 4; s++) acc[r][s] = 0.f;
#pragma unroll 16
    for (int cc = 0; cc < 64; cc++) {        // x @ M
        float4 bv = *(const float4*)&Ms[cc * 64 + 4 * tj];
        float b4[4] = {bv.x, bv.y, bv.z, bv.w};
        float a4[4];
#pragma unroll
        for (int r = 0; r < 4; r++) a4[r] = xs[(4 * ti + r) * 64 + cc];
#pragma unroll
        for (int r = 0; r < 4; r++)
#pragma unroll
            for (int s = 0; s < 4; s++) acc[r][s] += a4[r] * b4[s];
    }
#pragma unroll
    for (int r = 0; r < 4; r++) {            // conv2 + combine + store
        int pl = 4 * ti + r, py = pl >> 3, pxx = pl & 7;
        float cv[4] = {0.f, 0.f, 0.f, 0.f};
#pragma unroll
        for (int ky = 0; ky < 3; ky++)
#pragma unroll
            for (int kx = 0; kx < 3; kx++) {
                int k = ky * 3 + kx;
                float4 pv = *(const float4*)&p1[((py + ky) * 10 + pxx + kx) * 64 + 4 * tj];
                cv[0] += pv.x * wr[0][k];
                cv[1] += pv.y * wr[1][k];
                cv[2] += pv.z * wr[2][k];
                cv[3] += pv.w * wr[3][k];
            }
        float4 o;
        o.x = acc[r][0] + cv[0] + bps[4 * tj + 0];
        o.y = acc[r][1] + cv[1] + bps[4 * tj + 1];
        o.z = acc[r][2] + cv[2] + bps[4 * tj + 2];
        o.w = acc[r][3] + cv[3] + bps[4 * tj + 3];
        *(float4*)(out + (((size_t)(b * HH + y0 + py)) * WW + x0 + pxx) * 64 + 4 * tj) = o;
    }
}

// ---------------- launch ----------------
extern "C" void kernel_launch(void* const* d_in, const int* in_sizes, int n_in,
                              void* d_out, int out_size) {
    const float* x     = (const float*)d_in[0];
    const float* Wq    = (const float*)d_in[1];
    const float* Wk    = (const float*)d_in[2];
    const float* Wv    = (const float*)d_in[3];
    const float* resc  = (const float*)d_in[4];
    const float* Wproj = (const float*)d_in[5];
    const float* bproj = (const float*)d_in[6];
    const float* Wc1d  = (const float*)d_in[7];
    const float* bc1d  = (const float*)d_in[8];
    const float* Wpe1  = (const float*)d_in[9];
    const float* Wpe2  = (const float*)d_in[10];
    float* out = (float*)d_out;

    cudaFuncSetAttribute(k3_attn, cudaFuncAttributeMaxDynamicSharedMemorySize, (12288 + 128) * 4);
    cudaFuncSetAttribute(k4b_main, cudaFuncAttributeMaxDynamicSharedMemorySize, 25024 * 4);

    k0_zero<<<32, 256>>>();
    k1_S<<<64, 256>>>(x);
    k2_SQ<<<16, 256>>>(Wq, Wk);
    k3_attn<<<16, 256, (12288 + 128) * 4>>>(Wk, Wq, resc, Wproj, Wv, Wc1d);
    k4a_P<<<2048, 256>>>(x, bc1d);
    k4b_main<<<2048, 256, 25024 * 4>>>(x, bproj, Wpe1, Wpe2, out);
}

// round 7
// speedup vs baseline: 1.0045x; 1.0045x over previous
#include <cuda_runtime.h>
#include <math.h>

#define BATCH 2
#define HH 256
#define WW 256
#define CIN 64
#define HEADS 8
#define HD 512

// ---------------- scratch (device globals; no runtime allocation) ----------------
__device__ float g_S[BATCH * 64 * 64];        // xd^T xd per batch
__device__ float g_SQ[BATCH * 64 * HD];       // S @ Wq
__device__ float g_nk[BATCH * HD];
__device__ float g_nq[BATCH * HD];
__device__ float g_M[BATCH * 64 * 64];        // Wv @ A^T @ Wproj per batch
__device__ float g_Wp[64 * 64];               // Wv @ Wc1d
__device__ float g_P[(size_t)BATCH * HH * WW * 64];  // p_pre (33.5 MB)

// ---------------- K0: zero accumulated buffers ----------------
__global__ void k0_zero() {
    int i = blockIdx.x * blockDim.x + threadIdx.x;
    if (i < BATCH * 4096) { g_S[i] = 0.f; g_M[i] = 0.f; }
    if (i < 4096) g_Wp[i] = 0.f;
}

// ---------------- K1: S_b = xd^T xd, xd = avgpool2x2(x) ----------------
// grid 64: 32 blocks/batch, each owns 4 ds-rows (512 tokens)
__global__ void k1_S(const float* __restrict__ x) {
    __shared__ float xs[16 * 64];
    int b  = blockIdx.x >> 5;
    int r0 = (blockIdx.x & 31) * 4;
    int tid = threadIdx.x;
    int ti = tid >> 4, tj = tid & 15;
    float acc[4][4];
#pragma unroll
    for (int r = 0; r < 4; r++)
#pragma unroll
        for (int s = 0; s < 4; s++) acc[r][s] = 0.f;

    int c   = tid & 63;
    int tl0 = tid >> 6;  // 0..3
    for (int g = 0; g < 32; g++) {
        int row  = r0 + (g >> 3);
        int col0 = (g & 7) * 16;
#pragma unroll
        for (int it = 0; it < 4; it++) {
            int tl = it * 4 + tl0;
            int gx = (col0 + tl) * 2;
            int gy = row * 2;
            const float* p0 = x + (((size_t)b * HH + gy) * WW + gx) * 64 + c;
            xs[tl * 64 + c] = 0.25f * (p0[0] + p0[64] + p0[WW * 64] + p0[WW * 64 + 64]);
        }
        __syncthreads();
#pragma unroll
        for (int t = 0; t < 16; t++) {
            float4 av = *(const float4*)&xs[t * 64 + 4 * ti];
            float4 bv = *(const float4*)&xs[t * 64 + 4 * tj];
            float a4[4] = {av.x, av.y, av.z, av.w};
            float b4[4] = {bv.x, bv.y, bv.z, bv.w};
#pragma unroll
            for (int r = 0; r < 4; r++)
#pragma unroll
                for (int s = 0; s < 4; s++) acc[r][s] += a4[r] * b4[s];
        }
        __syncthreads();
    }
    float* Sb = g_S + b * 4096;
#pragma unroll
    for (int r = 0; r < 4; r++)
#pragma unroll
        for (int s = 0; s < 4; s++)
            atomicAdd(&Sb[(4 * ti + r) * 64 + 4 * tj + s], acc[r][s]);
}

// ---------------- K2: SQ = S@Wq (stored), norms nk/nq ----------------
// grid 16: (b, h)
__global__ void k2_SQ(const float* __restrict__ Wq, const float* __restrict__ Wk) {
    __shared__ float Ss[4096];
    __shared__ float Wc[4096];
    __shared__ float n2[64];
    int b = blockIdx.x >> 3, h = blockIdx.x & 7;
    int tid = threadIdx.x, ti = tid >> 4, tj = tid & 15;
    for (int u = tid; u < 4096; u += 256) Ss[u] = g_S[b * 4096 + u];

    for (int pass = 0; pass < 2; pass++) {
        const float* Wsrc = pass ? Wk : Wq;
        for (int u = tid; u < 4096; u += 256) {
            int cc = u >> 6, j = u & 63;
            Wc[u] = Wsrc[cc * HD + h * 64 + j];
        }
        if (tid < 64) n2[tid] = 0.f;
        __syncthreads();

        float acc[4][4];
#pragma unroll
        for (int r = 0; r < 4; r++)
#pragma unroll
            for (int s = 0; s < 4; s++) acc[r][s] = 0.f;
#pragma unroll 16
        for (int cc = 0; cc < 64; cc++) {
            float4 bv = *(const float4*)&Wc[cc * 64 + 4 * tj];
            float b4[4] = {bv.x, bv.y, bv.z, bv.w};
            float a4[4];
#pragma unroll
            for (int r = 0; r < 4; r++) a4[r] = Ss[(4 * ti + r) * 64 + cc];
#pragma unroll
            for (int r = 0; r < 4; r++)
#pragma unroll
                for (int s = 0; s < 4; s++) acc[r][s] += a4[r] * b4[s];
        }
        float psum[4] = {0.f, 0.f, 0.f, 0.f};
#pragma unroll
        for (int r = 0; r < 4; r++)
#pragma unroll
            for (int s = 0; s < 4; s++)
                psum[s] += Wc[(4 * ti + r) * 64 + 4 * tj + s] * acc[r][s];
        if (!pass) {
#pragma unroll
            for (int r = 0; r < 4; r++)
#pragma unroll
                for (int s = 0; s < 4; s++)
                    g_SQ[b * 32768 + (4 * ti + r) * HD + h * 64 + 4 * tj + s] = acc[r][s];
        }
#pragma unroll
        for (int s = 0; s < 4; s++) atomicAdd(&n2[4 * tj + s], psum[s]);
        __syncthreads();
        if (tid < 64) {
            float nv = fmaxf(sqrtf(fmaxf(n2[tid], 0.f)), 1e-12f);
            (pass ? g_nk : g_nq)[b * HD + h * 64 + tid] = nv;
        }
        __syncthreads();
    }
}

// ---------------- K3: attn -> M_b, and Wp = Wv@Wc1d ----------------
// grid 16: (b, h), dynamic smem = (12288 + 128) floats
__global__ void k3_attn(const float* __restrict__ Wk, const float* __restrict__ Wq,
                        const float* __restrict__ rescale, const float* __restrict__ Wproj,
                        const float* __restrict__ Wv, const float* __restrict__ Wc1d) {
    extern __shared__ float sm3[];
    float* bufA = sm3;
    float* bufB = sm3 + 4096;
    float* bufC = sm3 + 8192;
    float* nks  = sm3 + 12288;
    float* nqs  = nks + 64;
    int b = blockIdx.x >> 3, h = blockIdx.x & 7;
    int tid = threadIdx.x, ti = tid >> 4, tj = tid & 15;

    for (int u = tid; u < 4096; u += 256) {
        int cc = u >> 6, i = u & 63;
        bufA[u] = Wk[cc * HD + h * 64 + i];              // Wk_h [c][i]
        bufB[u] = g_SQ[b * 32768 + cc * HD + h * 64 + i]; // SQ_h [c][j]
    }
    if (tid < 64) { nks[tid] = g_nk[b * HD + h * 64 + tid]; nqs[tid] = g_nq[b * HD + h * 64 + tid]; }
    __syncthreads();
    float resc = rescale[h];

    float acc[4][4];
#pragma unroll
    for (int r = 0; r < 4; r++)
#pragma unroll
        for (int s = 0; s < 4; s++) acc[r][s] = 0.f;
#pragma unroll 16
    for (int cc = 0; cc < 64; cc++) {   // G[i][j] = sum_c Wk_h[c][i] * SQ_h[c][j]
        float4 av = *(const float4*)&bufA[cc * 64 + 4 * ti];
        float4 bv = *(const float4*)&bufB[cc * 64 + 4 * tj];
        float a4[4] = {av.x, av.y, av.z, av.w}, b4[4] = {bv.x, bv.y, bv.z, bv.w};
#pragma unroll
        for (int r = 0; r < 4; r++)
#pragma unroll
            for (int s = 0; s < 4; s++) acc[r][s] += a4[r] * b4[s];
    }
#pragma unroll
    for (int r = 0; r < 4; r++)
#pragma unroll
        for (int s = 0; s < 4; s++)
            bufC[(4 * ti + r) * 64 + 4 * tj + s] =
                acc[r][s] / (nks[4 * ti + r] * nqs[4 * tj + s]) * resc;
    __syncthreads();

    // overwrite bufA with Wproj_h [i][d]; softmax rows of bufC concurrently
    for (int u = tid; u < 4096; u += 256)
        bufA[u] = Wproj[(h * 64 + (u >> 6)) * 64 + (u & 63)];
    if (tid < 64) {
        float m = -1e30f;
        for (int j = 0; j < 64; j++) m = fmaxf(m, bufC[tid * 64 + j]);
        float ss = 0.f;
        for (int j = 0; j < 64; j++) { float e = expf(bufC[tid * 64 + j] - m); bufC[tid * 64 + j] = e; ss += e; }
        float inv = 1.f / ss;
        for (int j = 0; j < 64; j++) bufC[tid * 64 + j] *= inv;
    }
    __syncthreads();

    // B[j][d] = sum_i attn[i][j] * Wproj_h[i][d]   (into regs, then bufB)
#pragma unroll
    for (int r = 0; r < 4; r++)
#pragma unroll
        for (int s = 0; s < 4; s++) acc[r][s] = 0.f;
#pragma unroll 16
    for (int i = 0; i < 64; i++) {
        float4 av = *(const float4*)&bufC[i * 64 + 4 * ti];   // j = 4ti+r
        float4 bv = *(const float4*)&bufA[i * 64 + 4 * tj];   // d = 4tj+s
        float a4[4] = {av.x, av.y, av.z, av.w}, b4[4] = {bv.x, bv.y, bv.z, bv.w};
#pragma unroll
        for (int r = 0; r < 4; r++)
#pragma unroll
            for (int s = 0; s < 4; s++) acc[r][s] += a4[r] * b4[s];
    }
    __syncthreads();   // everyone done reading bufB (G stage long done), bufC reads done
#pragma unroll
    for (int r = 0; r < 4; r++)
#pragma unroll
        for (int s = 0; s < 4; s++) bufB[(4 * ti + r) * 64 + 4 * tj + s] = acc[r][s];
    for (int u = tid; u < 4096; u += 256)
        bufC[u] = Wv[(u >> 6) * HD + h * 64 + (u & 63)];      // Wv_h [c][j]
    __syncthreads();

    // C[c][d] = sum_j Wv_h[c][j] * B[j][d] -> atomic into g_M[b]
#pragma unroll
    for (int r = 0; r < 4; r++)
#pragma unroll
        for (int s = 0; s < 4; s++) acc[r][s] = 0.f;
#pragma unroll 16
    for (int j = 0; j < 64; j++) {
        float4 bv = *(const float4*)&bufB[j * 64 + 4 * tj];
        float b4[4] = {bv.x, bv.y, bv.z, bv.w};
        float a4[4];
#pragma unroll
        for (int r = 0; r < 4; r++) a4[r] = bufC[(4 * ti + r) * 64 + j];
#pragma unroll
        for (int r = 0; r < 4; r++)
#pragma unroll
            for (int s = 0; s < 4; s++) acc[r][s] += a4[r] * b4[s];
    }
#pragma unroll
    for (int r = 0; r < 4; r++)
#pragma unroll
        for (int s = 0; s < 4; s++)
            atomicAdd(&g_M[b * 4096 + (4 * ti + r) * 64 + 4 * tj + s], acc[r][s]);

    if (b == 0) {  // Wp = Wv @ Wc1d (batch independent): blocks of batch 0 only
        __syncthreads();
        for (int u = tid; u < 4096; u += 256)
            bufA[u] = Wc1d[(h * 64 + (u >> 6)) * 64 + (u & 63)];  // [j][d]
        __syncthreads();
#pragma unroll
        for (int r = 0; r < 4; r++)
#pragma unroll
            for (int s = 0; s < 4; s++) acc[r][s] = 0.f;
#pragma unroll 16
        for (int j = 0; j < 64; j++) {
            float4 bv = *(const float4*)&bufA[j * 64 + 4 * tj];
            float b4[4] = {bv.x, bv.y, bv.z, bv.w};
            float a4[4];
#pragma unroll
            for (int r = 0; r < 4; r++) a4[r] = bufC[(4 * ti + r) * 64 + j];
#pragma unroll
            for (int r = 0; r < 4; r++)
#pragma unroll
                for (int s = 0; s < 4; s++) acc[r][s] += a4[r] * b4[s];
        }
#pragma unroll
        for (int r = 0; r < 4; r++)
#pragma unroll
            for (int s = 0; s < 4; s++)
                atomicAdd(&g_Wp[(4 * ti + r) * 64 + 4 * tj + s], acc[r][s]);
    }
}

// ---------------- K4a: p_pre = x @ Wp + bc1d -> g_P ----------------
// grid 2048 blocks x 64 pixels
__global__ void k4a_P(const float* __restrict__ x, const float* __restrict__ bc1d) {
    __shared__ float Wps[4096];
    __shared__ float xs[4096];
    __shared__ float bc[64];
    int tid = threadIdx.x;
    for (int u = tid; u < 4096; u += 256) Wps[u] = g_Wp[u];
    if (tid < 64) bc[tid] = bc1d[tid];
    size_t base = (size_t)blockIdx.x * 4096;
    const float4* src = (const float4*)(x + base);
    for (int u = tid; u < 1024; u += 256) ((float4*)xs)[u] = src[u];
    __syncthreads();

    int ti = tid >> 4, tj = tid & 15;
    float acc[4][4];
#pragma unroll
    for (int r = 0; r < 4; r++)
#pragma unroll
        for (int s = 0; s < 4; s++) acc[r][s] = 0.f;
#pragma unroll 16
    for (int cc = 0; cc < 64; cc++) {
        float4 bv = *(const float4*)&Wps[cc * 64 + 4 * tj];
        float b4[4] = {bv.x, bv.y, bv.z, bv.w};
        float a4[4];
#pragma unroll
        for (int r = 0; r < 4; r++) a4[r] = xs[(4 * ti + r) * 64 + cc];
#pragma unroll
        for (int r = 0; r < 4; r++)
#pragma unroll
            for (int s = 0; s < 4; s++) acc[r][s] += a4[r] * b4[s];
    }
#pragma unroll
    for (int r = 0; r < 4; r++) {
        float4 o;
        o.x = acc[r][0] + bc[4 * tj + 0];
        o.y = acc[r][1] + bc[4 * tj + 1];
        o.z = acc[r][2] + bc[4 * tj + 2];
        o.w = acc[r][3] + bc[4 * tj + 3];
        *(float4*)(g_P + base + (size_t)(4 * ti + r) * 64 + 4 * tj) = o;
    }
}

// ---------------- K4b: conv1+GELU+conv2 + x@M + bproj -> out ----------------
// grid 2048: (b, 32x32 tiles of 8x8). dyn smem = 25024 floats
__global__ void k4b_main(const float* __restrict__ x, const float* __restrict__ bproj,
                         const float* __restrict__ Wpe1, const float* __restrict__ Wpe2,
                         float* __restrict__ out) {
    extern __shared__ float sm4[];
    float* ps  = sm4;          // 12x12x64 = 9216
    float* p1  = ps + 9216;    // 10x10x64 = 6400
    float* xs  = p1 + 6400;    // 8x8x64   = 4096
    float* Ms  = xs + 4096;    // 4096
    float* w1  = Ms + 4096;    // 576
    float* w2  = w1 + 576;     // 576
    float* bps = w2 + 576;     // 64
    int blk = blockIdx.x;
    int b = blk >> 10;
    int rem = blk & 1023;
    int y0 = (rem >> 5) * 8, x0 = (rem & 31) * 8;
    int tid = threadIdx.x;

    for (int u = tid; u < 4096; u += 256) Ms[u] = g_M[b * 4096 + u];
    for (int u = tid; u < 576; u += 256) { w1[u] = Wpe1[u]; w2[u] = Wpe2[u]; }
    if (tid < 64) bps[tid] = bproj[tid];
    for (int u = tid; u < 1024; u += 256) {  // interior x tile (8 rows x 512 floats)
        int py = u >> 7, off = u & 127;
        const float4* src = (const float4*)(x + (((size_t)(b * HH + y0 + py)) * WW + x0) * 64);
        ((float4*)xs)[py * 128 + off] = src[off];
    }
    for (int u = tid; u < 9216; u += 256) {  // halo p_pre with zero pad
        int px = u >> 6, c = u & 63;
        int py = px / 12, pxx = px - py * 12;
        int gy = y0 - 2 + py, gx = x0 - 2 + pxx;
        float v = 0.f;
        if ((unsigned)gy < HH && (unsigned)gx < WW)
            v = g_P[(((size_t)(b * HH + gy)) * WW + gx) * 64 + c];
        ps[u] = v;
    }
    __syncthreads();

    for (int u = tid; u < 6400; u += 256) {  // conv1 + exact GELU, zero outside image
        int px = u >> 6, c = u & 63;
        int py = px / 10, pxx = px - py * 10;
        int gy = y0 - 1 + py, gx = x0 - 1 + pxx;
        float v = 0.f;
        if ((unsigned)gy < HH && (unsigned)gx < WW) {
            float a = 0.f;
#pragma unroll
            for (int ky = 0; ky < 3; ky++)
#pragma unroll
                for (int kx = 0; kx < 3; kx++)
                    a += ps[((py + ky) * 12 + pxx + kx) * 64 + c] * w1[c * 9 + ky * 3 + kx];
            v = 0.5f * a * (1.f + erff(a * 0.70710678118654752f));
        }
        p1[u] = v;
    }
    __syncthreads();

    int ti = tid >> 4, tj = tid & 15;
    float wr[4][9];
#pragma unroll
    for (int s = 0; s < 4; s++)
#pragma unroll
        for (int k = 0; k < 9; k++) wr[s][k] = w2[(4 * tj + s) * 9 + k];

    float acc[4][4];
#pragma unroll
    for (int r = 0; r < 4; r++)
#pragma unroll
        for (int s = 0; s < 4; s++) acc[r][s] = 0.f;
#pragma unroll 16
    for (int cc = 0; cc < 64; cc++) {        // x @ M
        float4 bv = *(const float4*)&Ms[cc * 64 + 4 * tj];
        float b4[4] = {bv.x, bv.y, bv.z, bv.w};
        float a4[4];
#pragma unroll
        for (int r = 0; r < 4; r++) a4[r] = xs[(4 * ti + r) * 64 + cc];
#pragma unroll
        for (int r = 0; r < 4; r++)
#pragma unroll
            for (int s = 0; s < 4; s++) acc[r][s] += a4[r] * b4[s];
    }
#pragma unroll
    for (int r = 0; r < 4; r++) {            // conv2 + combine + store
        int pl = 4 * ti + r, py = pl >> 3, pxx = pl & 7;
        float cv[4] = {0.f, 0.f, 0.f, 0.f};
#pragma unroll
        for (int ky = 0; ky < 3; ky++)
#pragma unroll
            for (int kx = 0; kx < 3; kx++) {
                int k = ky * 3 + kx;
                float4 pv = *(const float4*)&p1[((py + ky) * 10 + pxx + kx) * 64 + 4 * tj];
                cv[0] += pv.x * wr[0][k];
                cv[1] += pv.y * wr[1][k];
                cv[2] += pv.z * wr[2][k];
                cv[3] += pv.w * wr[3][k];
            }
        float4 o;
        o.x = acc[r][0] + cv[0] + bps[4 * tj + 0];
        o.y = acc[r][1] + cv[1] + bps[4 * tj + 1];
        o.z = acc[r][2] + cv[2] + bps[4 * tj + 2];
        o.w = acc[r][3] + cv[3] + bps[4 * tj + 3];
        *(float4*)(out + (((size_t)(b * HH + y0 + py)) * WW + x0 + pxx) * 64 + 4 * tj) = o;
    }
}

// ---------------- launch ----------------
extern "C" void kernel_launch(void* const* d_in, const int* in_sizes, int n_in,
                              void* d_out, int out_size) {
    const float* x     = (const float*)d_in[0];
    const float* Wq    = (const float*)d_in[1];
    const float* Wk    = (const float*)d_in[2];
    const float* Wv    = (const float*)d_in[3];
    const float* resc  = (const float*)d_in[4];
    const float* Wproj = (const float*)d_in[5];
    const float* bproj = (const float*)d_in[6];
    const float* Wc1d  = (const float*)d_in[7];
    const float* bc1d  = (const float*)d_in[8];
    const float* Wpe1  = (const float*)d_in[9];
    const float* Wpe2  = (const float*)d_in[10];
    float* out = (float*)d_out;

    cudaFuncSetAttribute(k3_attn, cudaFuncAttributeMaxDynamicSharedMemorySize, (12288 + 128) * 4);
    cudaFuncSetAttribute(k4b_main, cudaFuncAttributeMaxDynamicSharedMemorySize, 25024 * 4);

    k0_zero<<<32, 256>>>();
    k1_S<<<64, 256>>>(x);
    k2_SQ<<<16, 256>>>(Wq, Wk);
    k3_attn<<<16, 256, (12288 + 128) * 4>>>(Wk, Wq, resc, Wproj, Wv, Wc1d);
    k4a_P<<<2048, 256>>>(x, bc1d);
    k4b_main<<<2048, 256, 25024 * 4>>>(x, bproj, Wpe1, Wpe2, out);
}